// round 15
// baseline (speedup 1.0000x reference)
#include <cuda_runtime.h>

#define KCLS 19
#define Bn 4
#define Cn 64
#define HWn 262144      // 512*512
#define EPSf 1e-5f
#define COUNTf 6.0f

// ---- stats: per-batch launch, 296 blocks = 2/SM, 64-px tiles via SMEM ----
#define SBLKS 296                 // stats blocks per launch (one batch)
#define TPX 64                    // pixels per tile
#define NTILES (HWn / TPX)        // 4096 tiles per batch
#define PAD 65                    // tile row stride (odd -> conflict-free)
#define BKC (KCLS * Cn)           // 1216

#define TA 1024                   // pixels per apply block

// ---- deterministic per-block partial scratch (no atomics anywhere) ----
// reused across batches (launches are sequential on the stream)
__device__ float g_s1p[SBLKS * BKC];
__device__ float g_s2p[SBLKS * BKC];
__device__ float g_cntp[SBLKS * KCLS];
__device__ float2 g_comb[Bn * KCLS * Cn];   // (scale, shift) per (b,k,c)

// ============================================================================
// Kernel 1 (per batch): per-(k,c) sum/sumsq. Coalesced LDG into registers,
// STS into pad-65 SMEM tile (64ch x 64px), then warp-uniform-class register
// binning with 2 CHANNELS PER LANE: warp w owns pixels p = w*8..w*8+7, lane
// owns channels {lane, lane+32}. One label read + one compare-tree dispatch
// per TWO values (halves the switch instruction bloat seen in R14).
// Register-buffered pipeline: LDG(t+1) issued before compute(t).
// ============================================================================
__global__ __launch_bounds__(256, 2) void stats_kernel(
    const float* __restrict__ x, const int* __restrict__ y, int b)
{
    __shared__ float xs[64 * PAD];     // value tile [c][p] at c*PAD+p
    __shared__ int4  ls4[TPX / 4];     // 64 labels
    __shared__ float msum[BKC];
    __shared__ float msq[BKC];
    __shared__ float scnt[KCLS];

    const int tid  = threadIdx.x;
    const int lane = tid & 31;
    const int w    = tid >> 5;         // warp -> 8-pixel subset
    const int tb   = blockIdx.x;       // 0..295

    const float* __restrict__ xb = x + (size_t)b * Cn * HWn;
    const int*   __restrict__ yb = y + (size_t)b * HWn;

    // staging roles: thread handles float4 chunks m = tid + k*256 (k=0..3),
    // chunk m: row c = m>>4, j = m&15 -> gmem xb[c*HW + t*64 + 4j]
    const int c0 = tid >> 4;
    const int j0 = tid & 15;

    float S0[KCLS], Q0[KCLS], S1[KCLS], Q1[KCLS];
#pragma unroll
    for (int j = 0; j < KCLS; j++) { S0[j]=0.f; Q0[j]=0.f; S1[j]=0.f; Q1[j]=0.f; }
    float cntf = 0.f;

    for (int i = tid; i < BKC; i += 256) { msum[i] = 0.f; msq[i] = 0.f; }
    if (tid < KCLS) scnt[tid] = 0.f;

    // ---- prologue: load tile tb into registers ----
    float4 vb0, vb1, vb2, vb3;
    int4 lb;
    {
        const float* base = xb + (size_t)tb * TPX;
        vb0 = *(const float4*)(base + (size_t)(c0     ) * HWn + 4 * j0);
        vb1 = *(const float4*)(base + (size_t)(c0 + 16) * HWn + 4 * j0);
        vb2 = *(const float4*)(base + (size_t)(c0 + 32) * HWn + 4 * j0);
        vb3 = *(const float4*)(base + (size_t)(c0 + 48) * HWn + 4 * j0);
        if (tid < 16) lb = ((const int4*)(yb + tb * TPX))[tid];
    }

#define CASE2(j) case j: S0[j] += v0; Q0[j] = fmaf(v0, v0, Q0[j]); \
                         S1[j] += v1; Q1[j] = fmaf(v1, v1, Q1[j]); break;

    for (int t = tb; t < NTILES; ) {
        __syncthreads();   // previous compute done (and init done on iter 0)
        // ---- store staged regs into tile ----
        {
            int base0 = (c0     ) * PAD + 4 * j0;
            int base1 = (c0 + 16) * PAD + 4 * j0;
            int base2 = (c0 + 32) * PAD + 4 * j0;
            int base3 = (c0 + 48) * PAD + 4 * j0;
            xs[base0] = vb0.x; xs[base0+1] = vb0.y; xs[base0+2] = vb0.z; xs[base0+3] = vb0.w;
            xs[base1] = vb1.x; xs[base1+1] = vb1.y; xs[base1+2] = vb1.z; xs[base1+3] = vb1.w;
            xs[base2] = vb2.x; xs[base2+1] = vb2.y; xs[base2+2] = vb2.z; xs[base2+3] = vb2.w;
            xs[base3] = vb3.x; xs[base3+1] = vb3.y; xs[base3+2] = vb3.z; xs[base3+3] = vb3.w;
            if (tid < 16) ls4[tid] = lb;
        }
        __syncthreads();

        // ---- issue next tile's loads early (overlap with compute) ----
        int tn = t + SBLKS;
        if (tn < NTILES) {
            const float* base = xb + (size_t)tn * TPX;
            vb0 = *(const float4*)(base + (size_t)(c0     ) * HWn + 4 * j0);
            vb1 = *(const float4*)(base + (size_t)(c0 + 16) * HWn + 4 * j0);
            vb2 = *(const float4*)(base + (size_t)(c0 + 32) * HWn + 4 * j0);
            vb3 = *(const float4*)(base + (size_t)(c0 + 48) * HWn + 4 * j0);
            if (tid < 16) lb = ((const int4*)(yb + tn * TPX))[tid];
        }

        // ---- compute: 8 pixels x 64 channels per warp, class warp-uniform ----
        const int* lsw = (const int*)ls4;
#pragma unroll
        for (int i = 0; i < 8; i++) {
            int p = w * 8 + i;
            int k = lsw[p];                          // warp-uniform broadcast
            float v0 = xs[lane * PAD + p];           // conflict-free (pad 65)
            float v1 = xs[(lane + 32) * PAD + p];
            cntf += (k == lane) ? 1.f : 0.f;         // each pixel counted once
            switch (k) {
                CASE2(0)  CASE2(1)  CASE2(2)  CASE2(3)  CASE2(4)
                CASE2(5)  CASE2(6)  CASE2(7)  CASE2(8)  CASE2(9)
                CASE2(10) CASE2(11) CASE2(12) CASE2(13) CASE2(14)
                CASE2(15) CASE2(16) CASE2(17) CASE2(18)
                default: break;
            }
        }
        t = tn;
    }
#undef CASE2

    // ---- block-level merge: serialized warp phases, no atomics ----
    __syncthreads();
    for (int ww = 0; ww < 8; ww++) {
        if (w == ww) {
#pragma unroll
            for (int j = 0; j < KCLS; j++) {
                msum[j * 64 + lane]      += S0[j];
                msum[j * 64 + lane + 32] += S1[j];
                msq [j * 64 + lane]      += Q0[j];
                msq [j * 64 + lane + 32] += Q1[j];
            }
            if (lane < KCLS) scnt[lane] += cntf;
        }
        __syncthreads();
    }
    float* s1p = g_s1p + (size_t)blockIdx.x * BKC;
    float* s2p = g_s2p + (size_t)blockIdx.x * BKC;
    for (int i = tid; i < BKC; i += 256) { s1p[i] = msum[i]; s2p[i] = msq[i]; }
    if (tid < KCLS) g_cntp[blockIdx.x * KCLS + tid] = scnt[tid];
}

// ============================================================================
// Kernel 2 (per batch): reduce 296 partials -> (scale, shift); style tails.
// grid = 19 blocks (one per class), 256 threads: 4 groups of 64 channels,
// each group sums 74 partials, SMEM-reduce the 4 groups.
// ============================================================================
__global__ void finalize_kernel(
    const float* __restrict__ style_means, const float* __restrict__ style_stds,
    float* __restrict__ dout, int b)
{
    __shared__ float rs1[4][64];
    __shared__ float rs2[4][64];
    __shared__ float rc[4];

    const int k   = blockIdx.x;           // 0..18
    const int tid = threadIdx.x;
    const int c   = tid & 63;
    const int q   = tid >> 6;             // 0..3

    float s1 = 0.f, s2 = 0.f, cnt = 0.f;
    for (int blk = q; blk < SBLKS; blk += 4) {
        size_t g = (size_t)blk * BKC + k * 64 + c;
        s1  += g_s1p[g];
        s2  += g_s2p[g];
        cnt += g_cntp[blk * KCLS + k];
    }
    rs1[q][c] = s1; rs2[q][c] = s2;
    if (c == 0) rc[q] = cnt;
    __syncthreads();

    if (q == 0) {
        s1  = rs1[0][c] + rs1[1][c] + rs1[2][c] + rs1[3][c];
        s2  = rs2[0][c] + rs2[1][c] + rs2[2][c] + rs2[3][c];
        cnt = rc[0] + rc[1] + rc[2] + rc[3];

        float cs   = fmaxf(cnt, 1.f);
        float mean = s1 / cs;
        float var  = (s2 - cs * mean * mean) / fmaxf(cnt - 1.f, 1.f);
        float stdc = sqrtf(fmaxf(var, 0.f)) + EPSf;
        bool valid = cnt > COUNTf;

        float sm = style_means[k * 64 + c];
        float ss = style_stds[k * 64 + c];
        float scale = valid ? (ss / stdc) : 1.f;
        float shift = valid ? (sm - mean * scale) : 0.f;
        int bk = b * KCLS + k;
        g_comb[bk * 64 + c] = make_float2(scale, shift);

        // output tails: style_means_1dim | style_stds_1dim | valid_bk
        float* o1 = dout + (size_t)Bn * Cn * HWn;
        float* o2 = o1 + Bn * KCLS * Cn;
        float* o3 = o2 + Bn * KCLS * Cn;
        o1[bk * 64 + c] = valid ? sm : 0.f;
        o2[bk * 64 + c] = valid ? ss : 0.f;
        if (c == 0) o3[bk] = valid ? 1.f : 0.f;
    }
}

// ============================================================================
// Kernel 3 (per batch): apply. out = x * scale[lab,c] + shift[lab,c].
// Runs right after stats_b so x_b (64 MB) is still L2-resident -> reads hit
// L2. Output stores use __stcs (evict-first streaming) so the write stream
// does not evict x_b. Labels in registers; (scale,shift) in pad-67 SMEM.
// ============================================================================
__global__ __launch_bounds__(256) void apply_kernel(
    const float* __restrict__ x, const int* __restrict__ y,
    float* __restrict__ out, int b)
{
    __shared__ float2 comb[KCLS * 67];

    const int tid = threadIdx.x;
    const int p0  = blockIdx.x * TA;

    for (int i = tid; i < KCLS * Cn; i += 256) {
        int k = i >> 6, c = i & 63;
        comb[k * 67 + c] = g_comb[(b * KCLS + k) * 64 + c];
    }
    int4 lb = ((const int4*)(y + (size_t)b * HWn + p0))[tid];
    __syncthreads();

    const float* xb = x + (size_t)b * Cn * HWn + p0;
    float*       ob = out + (size_t)b * Cn * HWn + p0;

#pragma unroll 4
    for (int c = 0; c < Cn; c++) {
        float4 v = ((const float4*)(xb + (size_t)c * HWn))[tid];
        float2 t0 = comb[lb.x * 67 + c];
        float2 t1 = comb[lb.y * 67 + c];
        float2 t2 = comb[lb.z * 67 + c];
        float2 t3 = comb[lb.w * 67 + c];
        float4 r;
        r.x = fmaf(v.x, t0.x, t0.y);
        r.y = fmaf(v.y, t1.x, t1.y);
        r.z = fmaf(v.z, t2.x, t2.y);
        r.w = fmaf(v.w, t3.x, t3.y);
        __stcs(((float4*)(ob + (size_t)c * HWn)) + tid, r);   // streaming store
    }
}

// ============================================================================
extern "C" void kernel_launch(void* const* d_in, const int* in_sizes, int n_in,
                              void* d_out, int out_size)
{
    const float* x  = (const float*)d_in[0];   // x_content [4,64,512,512] f32
    const int*   y  = (const int*)d_in[1];     // y_content [4,512,512] i32
    const float* sm = (const float*)d_in[2];   // style_means [19,64] f32
    const float* ss = (const float*)d_in[3];   // style_stds  [19,64] f32
    float* out = (float*)d_out;

    // per-batch pipeline: apply_b runs while x_b is still L2-resident
    for (int b = 0; b < Bn; b++) {
        stats_kernel<<<SBLKS, 256>>>(x, y, b);
        finalize_kernel<<<KCLS, 256>>>(sm, ss, out, b);
        apply_kernel<<<HWn / TA, 256>>>(x, y, out, b);
    }
}